// round 3
// baseline (speedup 1.0000x reference)
#include <cuda_runtime.h>

// CLSTM, direction=0: scan over D=64.
//   z  = relu(conv5x5(x_t,Wx)) + relu(conv5x5(h_prev,Wh)) + b   (channels 0,2,3)
//   i=sig(z0), cg=tanh(z2), o=sig(z3); c=(cg+c_prev)*i; h=o*tanh(c)
//
// Strategy:
//   Kernel 1 (parallel): zx[t] = relu(conv(x_t,Wx)) + b for all t, 3 channels.
//                        Also resets the progress flags (determinism across replays).
//   Kernel 2 (persistent): 256 blocks, one per (batch, 32x32 tile). c in registers.
//                        Per step: conv-h from gmem halo tile, gates, write h,
//                        fence, publish flag; wait only on 8 halo neighbors.

#define HH 256
#define WW 256
#define BB 4
#define TT 64
#define NPIX (HH * WW)

__device__ float g_zx[(size_t)BB * TT * 3 * NPIX];   // [b][t][c(0,2,3)][pix]
__device__ int   g_prog[256 * 32];                   // per-block flag, 128B apart

__device__ __forceinline__ float fast_tanh(float v) {
    float y; asm("tanh.approx.f32 %0, %1;" : "=f"(y) : "f"(v)); return y;
}
__device__ __forceinline__ float fast_sigmoid(float v) {
    return 0.5f * fast_tanh(0.5f * v) + 0.5f;
}

// ---------------------------------------------------------------------------
// Kernel 1: x-conv precompute, grid (8,8,BB*TT), block (32,8)
// ---------------------------------------------------------------------------
__global__ __launch_bounds__(256)
void clstm_xconv(const float* __restrict__ x,
                 const float* __restrict__ Wx,
                 const float* __restrict__ bias)
{
    __shared__ float xs[36 * 36];
    __shared__ float wsm[78];   // [0..24]=ch0, [25..49]=ch2, [50..74]=ch3, [75..77]=bias

    const int lane = threadIdx.x, ty = threadIdx.y;
    const int tid  = ty * 32 + lane;
    const int z    = blockIdx.z;               // b*TT + t
    const int x0   = blockIdx.x * 32;
    const int y0   = blockIdx.y * 32;

    // reset progress flags once per call (before the scan kernel runs)
    if (z == 0 && blockIdx.x == 0 && blockIdx.y == 0) g_prog[tid * 32] = 0;

    if (tid < 75)                 wsm[tid] = Wx[tid < 25 ? tid : tid + 25];
    else if (tid < 78) {
        int c = tid - 75;         // 0,1,2 -> bias ch 0,2,3
        wsm[tid] = bias[c == 0 ? 0 : c + 1];
    }

    const float* xsrc = x + (size_t)z * NPIX;

    #pragma unroll
    for (int pass = 0; pass < 6; pass++) {
        int idx = tid + pass * 256;
        if (idx < 36 * 36) {
            int rr = idx / 36, cc = idx % 36;
            int gy = y0 + rr - 2, gx = x0 + cc - 2;
            bool ok = (gy >= 0) && (gy < HH) && (gx >= 0) && (gx < WW);
            xs[idx] = ok ? xsrc[gy * WW + gx] : 0.0f;
        }
    }
    __syncthreads();

    float a0[4] = {0,0,0,0}, a2[4] = {0,0,0,0}, a3[4] = {0,0,0,0};
    const int rbase = ty * 4;

    #pragma unroll
    for (int ky = 0; ky < 5; ky++)
        #pragma unroll
        for (int kx = 0; kx < 5; kx++) {
            const int tap = ky * 5 + kx;
            const float w0 = wsm[tap], w2 = wsm[25 + tap], w3 = wsm[50 + tap];
            #pragma unroll
            for (int r = 0; r < 4; r++) {
                float v = xs[(rbase + r + ky) * 36 + lane + kx];
                a0[r] += w0 * v; a2[r] += w2 * v; a3[r] += w3 * v;
            }
        }

    float* zx = g_zx + (size_t)z * 3 * NPIX;
    const int gx = x0 + lane;
    #pragma unroll
    for (int r = 0; r < 4; r++) {
        const int pix = (y0 + rbase + r) * WW + gx;
        zx[0 * NPIX + pix] = fmaxf(a0[r], 0.f) + wsm[75];
        zx[1 * NPIX + pix] = fmaxf(a2[r], 0.f) + wsm[76];
        zx[2 * NPIX + pix] = fmaxf(a3[r], 0.f) + wsm[77];
    }
}

// ---------------------------------------------------------------------------
// Kernel 2: persistent scan. grid 256 blocks x 256 threads, all co-resident.
// ---------------------------------------------------------------------------
__global__ __launch_bounds__(256, 2)
void clstm_scan(const float* __restrict__ Wh,
                float* __restrict__ out)
{
    __shared__ float hs[36 * 36];
    __shared__ float wsm[75];
    __shared__ int   nbflag[8];
    __shared__ int   nbn_s;

    const int lane = threadIdx.x, ty = threadIdx.y;
    const int tid  = ty * 32 + lane;
    const int bid  = blockIdx.x;
    const int b    = bid >> 6;
    const int by   = (bid >> 3) & 7;
    const int bx   = bid & 7;
    const int x0   = bx * 32, y0 = by * 32;
    const int rbase = ty * 4;
    const int gx    = x0 + lane;

    if (tid < 75) wsm[tid] = Wh[tid < 25 ? tid : tid + 25];

    if (tid == 0) {
        int n = 0;
        #pragma unroll
        for (int dy = -1; dy <= 1; dy++)
            for (int dx = -1; dx <= 1; dx++) {
                if (dx == 0 && dy == 0) continue;
                int ny = by + dy, nx = bx + dx;
                if (ny >= 0 && ny < 8 && nx >= 0 && nx < 8)
                    nbflag[n++] = (((b << 3) | ny) << 3) | nx;
            }
        nbn_s = n;
    }

    const float b0 = 0.f;  (void)b0;
    float c0 = 0.f, c1 = 0.f, c2 = 0.f, c3 = 0.f;
    float creg[4] = {0,0,0,0};
    (void)c0; (void)c1; (void)c2; (void)c3;

    __syncthreads();
    const int nbn = nbn_s;

    for (int t = 0; t < TT; t++) {
        // --- prefetch zx for this step (independent of neighbor sync) ---
        const float* zx = g_zx + (size_t)(b * TT + t) * 3 * NPIX;
        float zx0[4], zx2[4], zx3[4];
        #pragma unroll
        for (int r = 0; r < 4; r++) {
            const int pix = (y0 + rbase + r) * WW + gx;
            zx0[r] = __ldg(zx + 0 * NPIX + pix);
            zx2[r] = __ldg(zx + 1 * NPIX + pix);
            zx3[r] = __ldg(zx + 2 * NPIX + pix);
        }

        float z0[4], z2[4], z3[4];

        if (t == 0) {
            #pragma unroll
            for (int r = 0; r < 4; r++) { z0[r] = zx0[r]; z2[r] = zx2[r]; z3[r] = zx3[r]; }
        } else {
            // --- wait for halo neighbors to finish step t-1 ---
            if (tid < nbn) {
                volatile int* f = &g_prog[nbflag[tid] * 32];
                while (*f < t) __nanosleep(40);
            }
            __syncthreads();
            __threadfence();

            // --- load h[t-1] tile (36x36, L2-fresh: bypass L1) ---
            const float* hsrc = out + (size_t)(b * TT + (t - 1)) * NPIX;
            #pragma unroll
            for (int pass = 0; pass < 6; pass++) {
                int idx = tid + pass * 256;
                if (idx < 36 * 36) {
                    int rr = idx / 36, cc = idx % 36;
                    int gy = y0 + rr - 2, gxx = x0 + cc - 2;
                    bool ok = (gy >= 0) && (gy < HH) && (gxx >= 0) && (gxx < WW);
                    hs[idx] = ok ? __ldcg(hsrc + gy * WW + gxx) : 0.0f;
                }
            }
            __syncthreads();

            float a0[4] = {0,0,0,0}, a2[4] = {0,0,0,0}, a3[4] = {0,0,0,0};
            #pragma unroll
            for (int ky = 0; ky < 5; ky++)
                #pragma unroll
                for (int kx = 0; kx < 5; kx++) {
                    const int tap = ky * 5 + kx;
                    const float w0 = wsm[tap], w2 = wsm[25 + tap], w3 = wsm[50 + tap];
                    #pragma unroll
                    for (int r = 0; r < 4; r++) {
                        float v = hs[(rbase + r + ky) * 36 + lane + kx];
                        a0[r] += w0 * v; a2[r] += w2 * v; a3[r] += w3 * v;
                    }
                }
            #pragma unroll
            for (int r = 0; r < 4; r++) {
                z0[r] = zx0[r] + fmaxf(a0[r], 0.f);
                z2[r] = zx2[r] + fmaxf(a2[r], 0.f);
                z3[r] = zx3[r] + fmaxf(a3[r], 0.f);
            }
            __syncthreads();   // hs reads done before next-iter overwrite
        }

        // --- gates + state update + h store ---
        float* optr = out + (size_t)(b * TT + t) * NPIX;
        #pragma unroll
        for (int r = 0; r < 4; r++) {
            float ig = fast_sigmoid(z0[r]);
            float cg = fast_tanh(z2[r]);
            float og = fast_sigmoid(z3[r]);
            float cn = (cg + creg[r]) * ig;
            creg[r] = cn;
            optr[(y0 + rbase + r) * WW + gx] = og * fast_tanh(cn);
        }

        // --- publish progress: all h stores fenced, then one flag store ---
        __threadfence();
        __syncthreads();
        if (tid == 0) *(volatile int*)&g_prog[bid * 32] = t + 1;
    }
}

// ---------------------------------------------------------------------------
extern "C" void kernel_launch(void* const* d_in, const int* in_sizes, int n_in,
                              void* d_out, int out_size)
{
    const float* x    = (const float*)d_in[0];
    const float* Wx   = (const float*)d_in[1];
    const float* Wh   = (const float*)d_in[2];
    const float* bias = (const float*)d_in[3];
    float* out        = (float*)d_out;

    dim3 blk(32, 8);
    dim3 g1(8, 8, BB * TT);
    clstm_xconv<<<g1, blk>>>(x, Wx, bias);

    clstm_scan<<<256, blk>>>(Wh, out);
}

// round 4
// speedup vs baseline: 1.0026x; 1.0026x over previous
#include <cuda_runtime.h>

// CLSTM, direction=0: scan over D=64.
//   z  = relu(conv5x5(x_t,Wx)) + relu(conv5x5(h_prev,Wh)) + b   (channels 0,2,3)
//   i=sig(z0), cg=tanh(z2), o=sig(z3); c=(cg+c_prev)*i; h=o*tanh(c)
//
// Strategy:
//   Kernel 1 (parallel): zx[t] = relu(conv(x_t,Wx)) + b for all t, 3 channels.
//                        Also resets the progress flags (determinism across replays).
//   Kernel 2 (persistent): 256 blocks, one per (batch, 32x32 tile). c in registers.
//                        Per step: conv-h from gmem halo tile, gates, write h,
//                        fence, publish flag; wait only on 8 halo neighbors.

#define HH 256
#define WW 256
#define BB 4
#define TT 64
#define NPIX (HH * WW)

__device__ float g_zx[(size_t)BB * TT * 3 * NPIX];   // [b][t][c(0,2,3)][pix]
__device__ int   g_prog[256 * 32];                   // per-block flag, 128B apart

__device__ __forceinline__ float fast_tanh(float v) {
    float y; asm("tanh.approx.f32 %0, %1;" : "=f"(y) : "f"(v)); return y;
}
__device__ __forceinline__ float fast_sigmoid(float v) {
    return 0.5f * fast_tanh(0.5f * v) + 0.5f;
}

// ---------------------------------------------------------------------------
// Kernel 1: x-conv precompute, grid (8,8,BB*TT), block (32,8)
// ---------------------------------------------------------------------------
__global__ __launch_bounds__(256)
void clstm_xconv(const float* __restrict__ x,
                 const float* __restrict__ Wx,
                 const float* __restrict__ bias)
{
    __shared__ float xs[36 * 36];
    __shared__ float wsm[78];   // [0..24]=ch0, [25..49]=ch2, [50..74]=ch3, [75..77]=bias

    const int lane = threadIdx.x, ty = threadIdx.y;
    const int tid  = ty * 32 + lane;
    const int z    = blockIdx.z;               // b*TT + t
    const int x0   = blockIdx.x * 32;
    const int y0   = blockIdx.y * 32;

    // reset progress flags once per call (before the scan kernel runs)
    if (z == 0 && blockIdx.x == 0 && blockIdx.y == 0) g_prog[tid * 32] = 0;

    if (tid < 75)                 wsm[tid] = Wx[tid < 25 ? tid : tid + 25];
    else if (tid < 78) {
        int c = tid - 75;         // 0,1,2 -> bias ch 0,2,3
        wsm[tid] = bias[c == 0 ? 0 : c + 1];
    }

    const float* xsrc = x + (size_t)z * NPIX;

    #pragma unroll
    for (int pass = 0; pass < 6; pass++) {
        int idx = tid + pass * 256;
        if (idx < 36 * 36) {
            int rr = idx / 36, cc = idx % 36;
            int gy = y0 + rr - 2, gx = x0 + cc - 2;
            bool ok = (gy >= 0) && (gy < HH) && (gx >= 0) && (gx < WW);
            xs[idx] = ok ? xsrc[gy * WW + gx] : 0.0f;
        }
    }
    __syncthreads();

    float a0[4] = {0,0,0,0}, a2[4] = {0,0,0,0}, a3[4] = {0,0,0,0};
    const int rbase = ty * 4;

    #pragma unroll
    for (int ky = 0; ky < 5; ky++)
        #pragma unroll
        for (int kx = 0; kx < 5; kx++) {
            const int tap = ky * 5 + kx;
            const float w0 = wsm[tap], w2 = wsm[25 + tap], w3 = wsm[50 + tap];
            #pragma unroll
            for (int r = 0; r < 4; r++) {
                float v = xs[(rbase + r + ky) * 36 + lane + kx];
                a0[r] += w0 * v; a2[r] += w2 * v; a3[r] += w3 * v;
            }
        }

    float* zx = g_zx + (size_t)z * 3 * NPIX;
    const int gx = x0 + lane;
    #pragma unroll
    for (int r = 0; r < 4; r++) {
        const int pix = (y0 + rbase + r) * WW + gx;
        zx[0 * NPIX + pix] = fmaxf(a0[r], 0.f) + wsm[75];
        zx[1 * NPIX + pix] = fmaxf(a2[r], 0.f) + wsm[76];
        zx[2 * NPIX + pix] = fmaxf(a3[r], 0.f) + wsm[77];
    }
}

// ---------------------------------------------------------------------------
// Kernel 2: persistent scan. grid 256 blocks x 256 threads, all co-resident.
// ---------------------------------------------------------------------------
__global__ __launch_bounds__(256, 2)
void clstm_scan(const float* __restrict__ Wh,
                float* __restrict__ out)
{
    __shared__ float hs[36 * 36];
    __shared__ float wsm[75];
    __shared__ int   nbflag[8];
    __shared__ int   nbn_s;

    const int lane = threadIdx.x, ty = threadIdx.y;
    const int tid  = ty * 32 + lane;
    const int bid  = blockIdx.x;
    const int b    = bid >> 6;
    const int by   = (bid >> 3) & 7;
    const int bx   = bid & 7;
    const int x0   = bx * 32, y0 = by * 32;
    const int rbase = ty * 4;
    const int gx    = x0 + lane;

    if (tid < 75) wsm[tid] = Wh[tid < 25 ? tid : tid + 25];

    if (tid == 0) {
        int n = 0;
        #pragma unroll
        for (int dy = -1; dy <= 1; dy++)
            for (int dx = -1; dx <= 1; dx++) {
                if (dx == 0 && dy == 0) continue;
                int ny = by + dy, nx = bx + dx;
                if (ny >= 0 && ny < 8 && nx >= 0 && nx < 8)
                    nbflag[n++] = (((b << 3) | ny) << 3) | nx;
            }
        nbn_s = n;
    }

    const float b0 = 0.f;  (void)b0;
    float c0 = 0.f, c1 = 0.f, c2 = 0.f, c3 = 0.f;
    float creg[4] = {0,0,0,0};
    (void)c0; (void)c1; (void)c2; (void)c3;

    __syncthreads();
    const int nbn = nbn_s;

    for (int t = 0; t < TT; t++) {
        // --- prefetch zx for this step (independent of neighbor sync) ---
        const float* zx = g_zx + (size_t)(b * TT + t) * 3 * NPIX;
        float zx0[4], zx2[4], zx3[4];
        #pragma unroll
        for (int r = 0; r < 4; r++) {
            const int pix = (y0 + rbase + r) * WW + gx;
            zx0[r] = __ldg(zx + 0 * NPIX + pix);
            zx2[r] = __ldg(zx + 1 * NPIX + pix);
            zx3[r] = __ldg(zx + 2 * NPIX + pix);
        }

        float z0[4], z2[4], z3[4];

        if (t == 0) {
            #pragma unroll
            for (int r = 0; r < 4; r++) { z0[r] = zx0[r]; z2[r] = zx2[r]; z3[r] = zx3[r]; }
        } else {
            // --- wait for halo neighbors to finish step t-1 ---
            if (tid < nbn) {
                volatile int* f = &g_prog[nbflag[tid] * 32];
                while (*f < t) __nanosleep(40);
            }
            __syncthreads();
            __threadfence();

            // --- load h[t-1] tile (36x36, L2-fresh: bypass L1) ---
            const float* hsrc = out + (size_t)(b * TT + (t - 1)) * NPIX;
            #pragma unroll
            for (int pass = 0; pass < 6; pass++) {
                int idx = tid + pass * 256;
                if (idx < 36 * 36) {
                    int rr = idx / 36, cc = idx % 36;
                    int gy = y0 + rr - 2, gxx = x0 + cc - 2;
                    bool ok = (gy >= 0) && (gy < HH) && (gxx >= 0) && (gxx < WW);
                    hs[idx] = ok ? __ldcg(hsrc + gy * WW + gxx) : 0.0f;
                }
            }
            __syncthreads();

            float a0[4] = {0,0,0,0}, a2[4] = {0,0,0,0}, a3[4] = {0,0,0,0};
            #pragma unroll
            for (int ky = 0; ky < 5; ky++)
                #pragma unroll
                for (int kx = 0; kx < 5; kx++) {
                    const int tap = ky * 5 + kx;
                    const float w0 = wsm[tap], w2 = wsm[25 + tap], w3 = wsm[50 + tap];
                    #pragma unroll
                    for (int r = 0; r < 4; r++) {
                        float v = hs[(rbase + r + ky) * 36 + lane + kx];
                        a0[r] += w0 * v; a2[r] += w2 * v; a3[r] += w3 * v;
                    }
                }
            #pragma unroll
            for (int r = 0; r < 4; r++) {
                z0[r] = zx0[r] + fmaxf(a0[r], 0.f);
                z2[r] = zx2[r] + fmaxf(a2[r], 0.f);
                z3[r] = zx3[r] + fmaxf(a3[r], 0.f);
            }
            __syncthreads();   // hs reads done before next-iter overwrite
        }

        // --- gates + state update + h store ---
        float* optr = out + (size_t)(b * TT + t) * NPIX;
        #pragma unroll
        for (int r = 0; r < 4; r++) {
            float ig = fast_sigmoid(z0[r]);
            float cg = fast_tanh(z2[r]);
            float og = fast_sigmoid(z3[r]);
            float cn = (cg + creg[r]) * ig;
            creg[r] = cn;
            optr[(y0 + rbase + r) * WW + gx] = og * fast_tanh(cn);
        }

        // --- publish progress: all h stores fenced, then one flag store ---
        __threadfence();
        __syncthreads();
        if (tid == 0) *(volatile int*)&g_prog[bid * 32] = t + 1;
    }
}

// ---------------------------------------------------------------------------
extern "C" void kernel_launch(void* const* d_in, const int* in_sizes, int n_in,
                              void* d_out, int out_size)
{
    const float* x    = (const float*)d_in[0];
    const float* Wx   = (const float*)d_in[1];
    const float* Wh   = (const float*)d_in[2];
    const float* bias = (const float*)d_in[3];
    float* out        = (float*)d_out;

    dim3 blk(32, 8);
    dim3 g1(8, 8, BB * TT);
    clstm_xconv<<<g1, blk>>>(x, Wx, bias);

    clstm_scan<<<256, blk>>>(Wh, out);
}